// round 13
// baseline (speedup 1.0000x reference)
#include <cuda_runtime.h>
#include <cstdint>

// CRF loss, bidirectional scaled forward algorithm, BOTH DIRECTIONS FUSED in
// one 64-thread CTA per batch row. Each period (one __syncthreads), thread g
// advances BOTH recurrences one step:
//   alpha: fwd column g, 26 fma.rn.f32x2 vs packed EA (E[i][g])
//   beta:  bwd row    g, 26 fma.rn.f32x2 vs packed EB (E[g][j])
// The two chains are independent -> barrier + LDS latency amortized over two
// steps. Exact pow-2 rescaling per step per side (pivot = max P[1..3]).
// Z = sum_i alpha_m[i] * beta_m[i] at the midpoint.

constexpr int TT = 50;
constexpr int LL = 256;
constexpr int NTH = 64;
constexpr int STARTT = TT - 2;
constexpr int STOPT  = TT - 1;

#define LOG2E 1.4426950408889634f
#define LN2F  0.6931471805599453f

__device__ float    g_partial[1024];
__device__ unsigned g_done = 0;

__device__ __forceinline__ float ex2(float x) {
    float r;
    asm("ex2.approx.ftz.f32 %0, %1;" : "=f"(r) : "f"(x));
    return r;
}

#define PACK2(d, lo, hi) \
    asm("mov.b64 %0, {%1, %2};" : "=l"(d) : "f"(lo), "f"(hi))
#define UNPACK2(lo, hi, s) \
    asm("mov.b64 {%0, %1}, %2;" : "=f"(lo), "=f"(hi) : "l"(s))
#define FFMA2(d, a, b, c) \
    asm("fma.rn.f32x2 %0, %1, %2, %3;" : "=l"(d) : "l"(a), "l"(b), "l"(c))
#define FMUL2(d, a, b) \
    asm("mul.rn.f32x2 %0, %1, %2;" : "=l"(d) : "l"(a), "l"(b))
#define FADD2(d, a, b) \
    asm("add.rn.f32x2 %0, %1, %2;" : "=l"(d) : "l"(a), "l"(b))
#define LDS_V2U64(q0, q1, addr) \
    asm volatile("ld.shared.v2.u64 {%0, %1}, [%2];" \
                 : "=l"(q0), "=l"(q1) : "r"(addr))

__device__ __forceinline__ float blockSum64(float v, volatile float* red) {
#pragma unroll
    for (int o = 16; o; o >>= 1) v += __shfl_xor_sync(0xffffffffu, v, o);
    if ((threadIdx.x & 31) == 0) red[threadIdx.x >> 5] = v;
    __syncthreads();
    v = red[0] + red[1];
    __syncthreads();
    return v;
}

__global__ void __launch_bounds__(NTH, 1)
crf_kernel(const float* __restrict__ feats, const float* __restrict__ trans,
           const int* __restrict__ tags, const int* __restrict__ mask,
           float* __restrict__ out) {
    __shared__ __align__(16) float Ab[2][64];   // alpha ping-pong
    __shared__ __align__(16) float Bb[2][64];   // beta  ping-pong
    __shared__ float red[2];
    __shared__ int s_len;
    __shared__ unsigned s_rank;

    const int b   = blockIdx.x;
    const int tid = threadIdx.x;
    const int g   = tid;
    const bool gv = (g < TT);
    const int gc  = gv ? g : (TT - 1);

    if (tid == 0) s_len = 0;
    __syncthreads();

    // ---- sequence length (mask is a 0/1 prefix) ----
    {
        const int4* m4 = (const int4*)(mask + (size_t)b * LL);
        int4 v = m4[tid];
        int c = (v.x != 0) + (v.y != 0) + (v.z != 0) + (v.w != 0);
#pragma unroll
        for (int o = 16; o; o >>= 1) c += __shfl_xor_sync(0xffffffffu, c, o);
        if ((tid & 31) == 0) atomicAdd(&s_len, c);
    }

    // ---- packed E slices:
    //   EA[x] = (exp trans[2x][g],   exp trans[2x+1][g])   -- fwd column g
    //   EB[x] = (exp trans[g][2x],   exp trans[g][2x+1])   -- bwd row    g
    uint64_t EA[26], EB[26];
#pragma unroll
    for (int x = 0; x < 26; x++) {
        int i0 = 2 * x, i1 = 2 * x + 1;
        float a0 = (gv && i0 < TT) ? ex2(trans[i0 * TT + gc] * LOG2E) : 0.f;
        float a1 = (gv && i1 < TT) ? ex2(trans[i1 * TT + gc] * LOG2E) : 0.f;
        float b0 = (gv && i0 < TT) ? ex2(trans[gc * TT + i0] * LOG2E) : 0.f;
        float b1 = (gv && i1 < TT) ? ex2(trans[gc * TT + i1] * LOG2E) : 0.f;
        PACK2(EA[x], a0, a1);
        PACK2(EB[x], b0, b1);
    }

    const float* fb = feats + (size_t)b * LL * TT;
    const float s0   = trans[STARTT * TT + 1];
    const float tref = trans[1 * TT + STOPT];
    const float C2f  = s0 * LOG2E;

    __syncthreads();
    const int len = s_len;
    const int nf  = (len - 1) >> 1;        // forward steps
    const int nb  = (len - 1) - nf;        // backward steps: nf or nf+1

    // ---- inits ----
    Ab[0][g] = gv ? ex2((fb[gc] + trans[STARTT * TT + gc] - s0) * LOG2E) : 0.f;
    {
        float w = gv ? ex2((trans[gc * TT + STOPT] - tref) * LOG2E) : 0.f;
        float f = (nb > 0) ? ex2(fb[(len - 1) * TT + gc] * LOG2E) : 1.f;
        Bb[0][g] = gv ? w * f : 0.f;
    }
    int kf = 0, kb = 0;
    int curf = 0, curb = 0;

    // ---- distance-2 prefetch for both directions (clamped) ----
    int rf1 = min(1, len - 1),          rf2 = min(2, len - 1);
    int rb1 = max(len - 2, 0),          rb2 = max(len - 3, 0);
    float fcf = fb[rf1 * TT + gc], fnf = fb[rf2 * TT + gc];
    float fcb = fb[rb1 * TT + gc], fnb = fb[rb2 * TT + gc];
    __syncthreads();

    // one fused period: advance alpha (if dof) and beta (if dob) one step
#define CRF_STEP2(EFA, EFB, DOF, DOB)                                       \
    {                                                                       \
        unsigned sa_ = (unsigned)__cvta_generic_to_shared(Ab[curf]);        \
        unsigned sb_ = (unsigned)__cvta_generic_to_shared(Bb[curb]);        \
        uint64_t qa0, qa1, qb0, qb1;                                        \
        LDS_V2U64(qa0, qa1, sa_);                                           \
        LDS_V2U64(qb0, qb1, sb_);                                           \
        float x0, x1, x2, x3;                                               \
        UNPACK2(x0, x1, qa0); UNPACK2(x2, x3, qa1);                         \
        float ma_ = fmaxf(fmaxf(x1, x2), x3);                               \
        UNPACK2(x0, x1, qb0); UNPACK2(x2, x3, qb1);                         \
        float mb_ = fmaxf(fmaxf(x1, x2), x3);                               \
        int ka_ = (__float_as_int(ma_) >> 23) - 127;                        \
        int kb_ = (__float_as_int(mb_) >> 23) - 127;                        \
        float sfa = __int_as_float((127 - ka_) << 23) * (EFA);              \
        float sfb = __int_as_float((127 - kb_) << 23) * (EFB);              \
        uint64_t fa0, fa1, fa2, fa3, ga0, ga1, ga2, ga3;                    \
        FMUL2(fa0, qa0, EA[0]); FMUL2(fa1, qa1, EA[1]);                     \
        FMUL2(ga0, qb0, EB[0]); FMUL2(ga1, qb1, EB[1]);                     \
        LDS_V2U64(qa0, qa1, sa_ + 16);                                      \
        LDS_V2U64(qb0, qb1, sb_ + 16);                                      \
        FMUL2(fa2, qa0, EA[2]); FMUL2(fa3, qa1, EA[3]);                     \
        FMUL2(ga2, qb0, EB[2]); FMUL2(ga3, qb1, EB[3]);                     \
        _Pragma("unroll")                                                   \
        for (int q = 2; q < 13; q++) {                                      \
            LDS_V2U64(qa0, qa1, sa_ + q * 16);                              \
            LDS_V2U64(qb0, qb1, sb_ + q * 16);                              \
            FFMA2(fa0, qa0, EA[2 * q], fa0);                                \
            FFMA2(fa1, qa1, EA[2 * q + 1], fa1);                            \
            FFMA2(ga0, qb0, EB[2 * q], ga0);                                \
            FFMA2(ga1, qb1, EB[2 * q + 1], ga1);                            \
            uint64_t t_;                                                    \
            t_ = fa0; fa0 = fa2; fa2 = t_;                                  \
            t_ = fa1; fa1 = fa3; fa3 = t_;                                  \
            t_ = ga0; ga0 = ga2; ga2 = t_;                                  \
            t_ = ga1; ga1 = ga3; ga3 = t_;                                  \
        }                                                                   \
        FADD2(fa0, fa0, fa2); FADD2(fa1, fa1, fa3); FADD2(fa0, fa0, fa1);   \
        FADD2(ga0, ga0, ga2); FADD2(ga1, ga1, ga3); FADD2(ga0, ga0, ga1);   \
        float la_, ha_;                                                     \
        if (DOF) {                                                          \
            UNPACK2(la_, ha_, fa0);                                         \
            Ab[curf ^ 1][g] = (la_ + ha_) * sfa;                            \
            kf += ka_; curf ^= 1;                                           \
        }                                                                   \
        if (DOB) {                                                          \
            UNPACK2(la_, ha_, ga0);                                         \
            Bb[curb ^ 1][g] = (la_ + ha_) * sfb;                            \
            kb += kb_; curb ^= 1;                                           \
        }                                                                   \
        __syncthreads();                                                    \
    }

    for (int s = 1; s <= nf; ++s) {
        float efa = ex2(fcf * LOG2E);
        float efb = (s == nb) ? 1.0f : ex2(fcb * LOG2E);  // beta_m: no ef_m
        fcf = fnf; fcb = fnb;
        int rf = min(s + 2, len - 1);
        int rb = max(len - 3 - s, 0);
        fnf = fb[rf * TT + gc];
        fnb = fb[rb * TT + gc];
        CRF_STEP2(efa, efb, true, true);
    }
    if (nb > nf) {                      // nb == nf + 1: peeled beta-only step
        CRF_STEP2(1.0f, 1.0f, false, true);
    }
#undef CRF_STEP2

    // ---- combine at the midpoint: Z = sum_i alpha_m[i] * beta_m[i] ----
    float z = Ab[curf][g] * Bb[curb][g];
    float sumv = blockSum64(z, red);
    float fwd = (log2f(sumv) + C2f + (float)(kf + kb)) * LN2F + tref;

    // ---- gold score ----
    const int* tgb = tags + (size_t)b * LL;
    float gl = 0.f;
    for (int t = tid; t < len; t += NTH) {
        int tg = tgb[t];
        int pv = (t == 0) ? STARTT : tgb[t - 1];
        gl += fb[t * TT + tg] + trans[pv * TT + tg];
    }
    float gold = blockSum64(gl, red);

    if (tid == 0) {
        gold += trans[tgb[len - 1] * TT + STOPT];
        g_partial[b] = fwd - gold;
    }

    // ---- fused finalize: last CTA sums all partials (fixed order) ----
    __threadfence();
    if (tid == 0) s_rank = atomicAdd(&g_done, 1u);
    __syncthreads();
    if (s_rank == gridDim.x - 1) {
        const int B = gridDim.x;
        if (tid < 32) {
            float acc = 0.f;
            for (int i = tid; i < B; i += 32) {
                float v;
                asm volatile("ld.global.cg.f32 %0, [%1];" : "=f"(v)
                             : "l"(&g_partial[i]));
                acc += v;
            }
#pragma unroll
            for (int o = 16; o; o >>= 1)
                acc += __shfl_xor_sync(0xffffffffu, acc, o);
            if (tid == 0) {
                *out = acc;
                g_done = 0;   // reset for next graph replay
            }
        }
    }
}

extern "C" void kernel_launch(void* const* d_in, const int* in_sizes, int n_in,
                              void* d_out, int out_size) {
    const float* feats = (const float*)d_in[0];
    const float* trans = (const float*)d_in[1];
    const int*   tags  = (const int*)d_in[2];
    const int*   mask  = (const int*)d_in[3];
    int B = in_sizes[0] / (LL * TT);

    crf_kernel<<<B, NTH>>>(feats, trans, tags, mask, (float*)d_out);
}